// round 3
// baseline (speedup 1.0000x reference)
#include <cuda_runtime.h>

#define BB 4
#define NN 8192
#define THREADS 256
#define UQ 4            // queries per thread
#define QBLOCKS 8       // 8 * 256 * 4 = 8192 query coverage
#define MSLICES 4
#define CHUNK 1024      // float4 db entries staged in smem (16KB)
#define FBLOCKS 64      // finalize blocks

// Scratch (device globals: no allocations allowed)
__device__ float4 g_q [2][BB][NN];  // [0]=clean query (c, |c|^2), [1]=pred query (p, |p|^2)
__device__ float4 g_db[2][BB][NN];  // [0]=pred db (-2p, |p|^2),   [1]=clean db (-2c, |c|^2)
__device__ float  g_minbuf[2][BB][NN];
__device__ int    g_nv[BB];
__device__ float  g_l1sum;
__device__ float  g_cd;
__device__ int    g_ticket;

__device__ __forceinline__ void atomicMinFloat(float* addr, float value) {
    if (value >= 0.0f)
        atomicMin((int*)addr, __float_as_int(value));
    else
        atomicMax((unsigned int*)addr, __float_as_uint(value));
}

__global__ void init_kernel() {
    int idx = blockIdx.x * blockDim.x + threadIdx.x;
    if (idx < 2 * BB * NN)
        ((float*)g_minbuf)[idx] = __int_as_float(0x7F800000);  // +inf
    if (idx < BB) g_nv[idx] = 0;
    if (idx == 0) { g_l1sum = 0.0f; g_cd = 0.0f; g_ticket = 0; }
}

__global__ void prep_kernel(const float* __restrict__ pred,
                            const float* __restrict__ target,
                            const int*   __restrict__ mask,
                            const float* __restrict__ points) {
    int gid = blockIdx.x * blockDim.x + threadIdx.x;   // grid exactly covers BB*NN
    int b = gid / NN;
    int base = gid * 3;
    float p0 = pred[base], p1 = pred[base + 1], p2 = pred[base + 2];
    float t0 = target[base], t1 = target[base + 1], t2 = target[base + 2];
    int m = mask[gid];
    float li = 0.0f;
    if (m) {
        li = (fabsf(p0 - t0) + fabsf(p1 - t1) + fabsf(p2 - t2)) * (1.0f / 3.0f);
        float x0 = points[base], x1 = points[base + 1], x2 = points[base + 2];
        float c0 = x0 + t0, c1 = x1 + t1, c2 = x2 + t2;     // clean
        float q0 = x0 + p0, q1 = x1 + p1, q2 = x2 + p2;     // predp
        float cn = fmaf(c0, c0, fmaf(c1, c1, c2 * c2));
        float pn = fmaf(q0, q0, fmaf(q1, q1, q2 * q2));
        int slot = atomicAdd(&g_nv[b], 1);
        g_q [0][b][slot] = make_float4(c0, c1, c2, cn);
        g_q [1][b][slot] = make_float4(q0, q1, q2, pn);
        g_db[0][b][slot] = make_float4(-2.0f * q0, -2.0f * q1, -2.0f * q2, pn);
        g_db[1][b][slot] = make_float4(-2.0f * c0, -2.0f * c1, -2.0f * c2, cn);
    }
    // warp-reduce l1 partial, one atomic per warp
    #pragma unroll
    for (int o = 16; o; o >>= 1) li += __shfl_down_sync(0xFFFFFFFFu, li, o);
    if ((threadIdx.x & 31) == 0) atomicAdd(&g_l1sum, li);
}

__global__ void __launch_bounds__(THREADS)
pair_kernel() {
    int z = blockIdx.z;
    int dir = z & 1;
    int b = z >> 1;
    int nv = g_nv[b];
    int qbase = blockIdx.x * (THREADS * UQ);
    if (qbase >= nv) return;                          // block-uniform
    int len = (nv + MSLICES - 1) / MSLICES;
    int m0 = blockIdx.y * len;
    int m1 = min(m0 + len, nv);
    if (m0 >= m1) return;                             // block-uniform

    __shared__ float4 sdb[CHUNK];

    const float4* __restrict__ Q  = g_q[dir][b];
    const float4* __restrict__ DB = g_db[dir][b];

    float qx[UQ], qy[UQ], qz[UQ], mn[UQ];
    #pragma unroll
    for (int u = 0; u < UQ; u++) {
        int qi = qbase + u * THREADS + threadIdx.x;
        float4 q = (qi < nv) ? Q[qi] : make_float4(0.f, 0.f, 0.f, 0.f);
        qx[u] = q.x; qy[u] = q.y; qz[u] = q.z;
        mn[u] = 3.4e38f;
    }

    for (int mc = m0; mc < m1; mc += CHUNK) {
        int cnt = min(CHUNK, m1 - mc);
        __syncthreads();
        for (int t = threadIdx.x; t < cnt; t += THREADS) sdb[t] = DB[mc + t];
        __syncthreads();
        #pragma unroll 4
        for (int j = 0; j < cnt; j++) {
            float4 p = sdb[j];                        // broadcast, conflict-free
            #pragma unroll
            for (int u = 0; u < UQ; u++) {
                // e = |p|^2 - 2*dot(p, q)   (query norm folded in at finalize)
                float e = fmaf(p.x, qx[u], fmaf(p.y, qy[u], fmaf(p.z, qz[u], p.w)));
                mn[u] = fminf(mn[u], e);
            }
        }
    }

    #pragma unroll
    for (int u = 0; u < UQ; u++) {
        int qi = qbase + u * THREADS + threadIdx.x;
        if (qi < nv) atomicMinFloat(&g_minbuf[dir][b][qi], mn[u]);
    }
}

__global__ void __launch_bounds__(256)
finalize_kernel(float* __restrict__ out) {
    __shared__ float red[256];
    const int total = 2 * BB * NN;
    float acc = 0.0f;
    // cache per-batch reciprocals
    float inv_nv[BB];
    #pragma unroll
    for (int b = 0; b < BB; b++) {
        int nv = g_nv[b];
        inv_nv[b] = (nv > 0) ? (1.0f / (float)nv) : 0.0f;
    }
    for (int idx = blockIdx.x * 256 + threadIdx.x; idx < total; idx += FBLOCKS * 256) {
        int dir = idx / (BB * NN);
        int r = idx % (BB * NN);
        int b = r / NN;
        int i = r % NN;
        if (i < g_nv[b]) {
            float e  = g_minbuf[dir][b][i];
            float qw = g_q[dir][b][i].w;
            float v  = fmaxf(qw + e, 0.0f);           // d2 clamp, monotone-commuted past the min
            acc = fmaf(v, inv_nv[b], acc);
        }
    }
    // block reduction
    red[threadIdx.x] = acc;
    __syncthreads();
    #pragma unroll
    for (int s = 128; s > 0; s >>= 1) {
        if (threadIdx.x < s) red[threadIdx.x] += red[threadIdx.x + s];
        __syncthreads();
    }
    if (threadIdx.x == 0) {
        atomicAdd(&g_cd, red[0]);
        __threadfence();
        int ticket = atomicAdd(&g_ticket, 1);
        if (ticket == FBLOCKS - 1) {
            int cnt = g_nv[0] + g_nv[1] + g_nv[2] + g_nv[3];
            float l1 = g_l1sum / (float)max(cnt, 1);
            float cd = g_cd / (float)BB;
            out[0] = 0.5f * (l1 + cd);
        }
    }
}

extern "C" void kernel_launch(void* const* d_in, const int* in_sizes, int n_in,
                              void* d_out, int out_size) {
    const float* pred   = (const float*)d_in[0];
    const float* target = (const float*)d_in[1];
    const int*   mask   = (const int*)d_in[2];
    const float* points = (const float*)d_in[3];

    init_kernel<<<(2 * BB * NN + 255) / 256, 256>>>();
    prep_kernel<<<(BB * NN) / 256, 256>>>(pred, target, mask, points);
    pair_kernel<<<dim3(QBLOCKS, MSLICES, 2 * BB), THREADS>>>();
    finalize_kernel<<<FBLOCKS, 256>>>((float*)d_out);
}

// round 4
// speedup vs baseline: 1.0052x; 1.0052x over previous
#include <cuda_runtime.h>

#define BB 4
#define NN 8192
#define THREADS 256
#define UQ 4            // queries per thread
#define QBLOCKS 8       // 8 * 256 * 4 = 8192 query coverage
#define MSLICES 4
#define CHUNK 1024      // float4 db entries staged in smem (16KB)
#define FBLOCKS 64      // finalize blocks

// Scratch (device globals: no allocations allowed)
__device__ float4 g_q [2][BB][NN];  // [0]=clean query (c, |c|^2), [1]=pred query (p, |p|^2)
__device__ float4 g_db[2][BB][NN];  // [0]=pred db (-2p, |p|^2),   [1]=clean db (-2c, |c|^2)
__device__ float  g_minbuf[2][BB][NN];
__device__ int    g_nv[BB];
__device__ float  g_l1sum;
__device__ float  g_cd;
__device__ int    g_ticket;

__device__ __forceinline__ void atomicMinFloat(float* addr, float value) {
    if (value >= 0.0f)
        atomicMin((int*)addr, __float_as_int(value));
    else
        atomicMax((unsigned int*)addr, __float_as_uint(value));
}

__global__ void init_kernel() {
    int idx = blockIdx.x * blockDim.x + threadIdx.x;
    if (idx < 2 * BB * NN)
        ((float*)g_minbuf)[idx] = __int_as_float(0x7F800000);  // +inf
    if (idx < BB) g_nv[idx] = 0;
    if (idx == 0) { g_l1sum = 0.0f; g_cd = 0.0f; g_ticket = 0; }
}

__global__ void prep_kernel(const float* __restrict__ pred,
                            const float* __restrict__ target,
                            const int*   __restrict__ mask,
                            const float* __restrict__ points) {
    int gid = blockIdx.x * blockDim.x + threadIdx.x;   // grid exactly covers BB*NN
    int b = gid / NN;
    int base = gid * 3;
    float p0 = pred[base], p1 = pred[base + 1], p2 = pred[base + 2];
    float t0 = target[base], t1 = target[base + 1], t2 = target[base + 2];
    int m = mask[gid];
    float li = 0.0f;
    if (m) {
        li = (fabsf(p0 - t0) + fabsf(p1 - t1) + fabsf(p2 - t2)) * (1.0f / 3.0f);
        float x0 = points[base], x1 = points[base + 1], x2 = points[base + 2];
        float c0 = x0 + t0, c1 = x1 + t1, c2 = x2 + t2;     // clean
        float q0 = x0 + p0, q1 = x1 + p1, q2 = x2 + p2;     // predp
        float cn = fmaf(c0, c0, fmaf(c1, c1, c2 * c2));
        float pn = fmaf(q0, q0, fmaf(q1, q1, q2 * q2));
        int slot = atomicAdd(&g_nv[b], 1);
        g_q [0][b][slot] = make_float4(c0, c1, c2, cn);
        g_q [1][b][slot] = make_float4(q0, q1, q2, pn);
        g_db[0][b][slot] = make_float4(-2.0f * q0, -2.0f * q1, -2.0f * q2, pn);
        g_db[1][b][slot] = make_float4(-2.0f * c0, -2.0f * c1, -2.0f * c2, cn);
    }
    // warp-reduce l1 partial, one atomic per warp
    #pragma unroll
    for (int o = 16; o; o >>= 1) li += __shfl_down_sync(0xFFFFFFFFu, li, o);
    if ((threadIdx.x & 31) == 0) atomicAdd(&g_l1sum, li);
}

__global__ void __launch_bounds__(THREADS)
pair_kernel() {
    int z = blockIdx.z;
    int dir = z & 1;
    int b = z >> 1;
    int nv = g_nv[b];
    int qbase = blockIdx.x * (THREADS * UQ);
    if (qbase >= nv) return;                          // block-uniform
    int len = (nv + MSLICES - 1) / MSLICES;
    int m0 = blockIdx.y * len;
    int m1 = min(m0 + len, nv);
    if (m0 >= m1) return;                             // block-uniform

    __shared__ float4 sdb[CHUNK];

    const float4* __restrict__ Q  = g_q[dir][b];
    const float4* __restrict__ DB = g_db[dir][b];

    float qx[UQ], qy[UQ], qz[UQ], mn[UQ];
    #pragma unroll
    for (int u = 0; u < UQ; u++) {
        int qi = qbase + u * THREADS + threadIdx.x;
        float4 q = (qi < nv) ? Q[qi] : make_float4(0.f, 0.f, 0.f, 0.f);
        qx[u] = q.x; qy[u] = q.y; qz[u] = q.z;
        mn[u] = 3.4e38f;
    }

    for (int mc = m0; mc < m1; mc += CHUNK) {
        int cnt = min(CHUNK, m1 - mc);
        __syncthreads();
        for (int t = threadIdx.x; t < cnt; t += THREADS) sdb[t] = DB[mc + t];
        __syncthreads();
        #pragma unroll 4
        for (int j = 0; j < cnt; j++) {
            float4 p = sdb[j];                        // broadcast, conflict-free
            #pragma unroll
            for (int u = 0; u < UQ; u++) {
                // e = |p|^2 - 2*dot(p, q)   (query norm folded in at finalize)
                float e = fmaf(p.x, qx[u], fmaf(p.y, qy[u], fmaf(p.z, qz[u], p.w)));
                mn[u] = fminf(mn[u], e);
            }
        }
    }

    #pragma unroll
    for (int u = 0; u < UQ; u++) {
        int qi = qbase + u * THREADS + threadIdx.x;
        if (qi < nv) atomicMinFloat(&g_minbuf[dir][b][qi], mn[u]);
    }
}

__global__ void __launch_bounds__(256)
finalize_kernel(float* __restrict__ out) {
    __shared__ float red[256];
    const int total = 2 * BB * NN;
    float acc = 0.0f;
    // cache per-batch reciprocals
    float inv_nv[BB];
    #pragma unroll
    for (int b = 0; b < BB; b++) {
        int nv = g_nv[b];
        inv_nv[b] = (nv > 0) ? (1.0f / (float)nv) : 0.0f;
    }
    for (int idx = blockIdx.x * 256 + threadIdx.x; idx < total; idx += FBLOCKS * 256) {
        int dir = idx / (BB * NN);
        int r = idx % (BB * NN);
        int b = r / NN;
        int i = r % NN;
        if (i < g_nv[b]) {
            float e  = g_minbuf[dir][b][i];
            float qw = g_q[dir][b][i].w;
            float v  = fmaxf(qw + e, 0.0f);           // d2 clamp, monotone-commuted past the min
            acc = fmaf(v, inv_nv[b], acc);
        }
    }
    // block reduction
    red[threadIdx.x] = acc;
    __syncthreads();
    #pragma unroll
    for (int s = 128; s > 0; s >>= 1) {
        if (threadIdx.x < s) red[threadIdx.x] += red[threadIdx.x + s];
        __syncthreads();
    }
    if (threadIdx.x == 0) {
        atomicAdd(&g_cd, red[0]);
        __threadfence();
        int ticket = atomicAdd(&g_ticket, 1);
        if (ticket == FBLOCKS - 1) {
            int cnt = g_nv[0] + g_nv[1] + g_nv[2] + g_nv[3];
            float l1 = g_l1sum / (float)max(cnt, 1);
            float cd = g_cd / (float)BB;
            out[0] = 0.5f * (l1 + cd);
        }
    }
}

extern "C" void kernel_launch(void* const* d_in, const int* in_sizes, int n_in,
                              void* d_out, int out_size) {
    const float* pred   = (const float*)d_in[0];
    const float* target = (const float*)d_in[1];
    const int*   mask   = (const int*)d_in[2];
    const float* points = (const float*)d_in[3];

    init_kernel<<<(2 * BB * NN + 255) / 256, 256>>>();
    prep_kernel<<<(BB * NN) / 256, 256>>>(pred, target, mask, points);
    pair_kernel<<<dim3(QBLOCKS, MSLICES, 2 * BB), THREADS>>>();
    finalize_kernel<<<FBLOCKS, 256>>>((float*)d_out);
}